// round 4
// baseline (speedup 1.0000x reference)
#include <cuda_runtime.h>
#include <cstdint>

// ---------------------------------------------------------------------------
// SelectiveSSM: xz = x@W_in^T ; conv+SiLU ; proj = xc@W_xproj^T ;
// combine (bc = sum(Bm*Cm), y = (softplus(dproj)*bc + D)*xc*silu(z)) ;
// out = y@W_out^T
// All GEMMs: C[M,N] = A[M,K] * B[N,K]^T, K-contiguous both operands.
// TF32 tensor-core GEMM (mma.sync.m16n8k8), fp32 accumulate.
// ---------------------------------------------------------------------------

#define D_STATE 16
#define BSZ     2
#define LSEQ    4096
#define DMODEL  1024
#define DINNER  2048
#define NROWS   (BSZ * LSEQ)            // 8192
#define NXZ     (2 * DINNER)            // 4096
#define NPROJ   (2 * D_STATE + DINNER)  // 2080

// Scratch (device globals: allocation-free)
__device__ float g_xz[NROWS * (size_t)NXZ];      // 134 MB
__device__ float g_xc[NROWS * (size_t)DINNER];   // 67 MB
__device__ float g_proj[NROWS * (size_t)NPROJ];  // 68 MB
__device__ float g_y[NROWS * (size_t)DINNER];    // 67 MB

// ---------------------------------------------------------------------------
// TF32 GEMM
// ---------------------------------------------------------------------------
#define BM 128
#define BN 128
#define BK 32

__device__ __forceinline__ uint32_t f2tf(float x) {
    uint32_t u;
    asm("cvt.rna.tf32.f32 %0, %1;" : "=r"(u) : "f"(x));
    return u;
}

// smem layout (per buffer, units of u32):
//   As[kstep(4)][mtile(8)][lane(32)][4 regs]   = 4096 u32 (16 KB)
//   Bs[kstep(4)][ntile(16)][lane(32)][2 regs]  = 4096 u32 (16 KB)
// Fragment-native: inner loop does one LDS.128 per A frag, LDS.64 per B frag.
__device__ __forceinline__ int aidx(int row, int k) {
    int kstep = k >> 3, kin = k & 7;
    int mtile = row >> 4, r = row & 15;
    int ln  = ((r & 7) << 2) | (kin & 3);
    int reg = ((kin >> 2) << 1) | (r >> 3);
    return ((((kstep << 3) + mtile) << 5) + ln) * 4 + reg;
}
__device__ __forceinline__ int bidx(int row, int k) {
    int kstep = k >> 3, kin = k & 7;
    int ntile = row >> 3, nin = row & 7;
    int ln  = (nin << 2) | (kin & 3);
    int reg = kin >> 2;
    return ((((kstep << 4) + ntile) << 5) + ln) * 2 + reg;
}

__device__ __forceinline__ void mma8(float acc[4], const uint32_t a[4], const uint32_t b[2]) {
    asm volatile(
        "mma.sync.aligned.m16n8k8.row.col.f32.tf32.tf32.f32 "
        "{%0,%1,%2,%3}, {%4,%5,%6,%7}, {%8,%9}, {%0,%1,%2,%3};"
        : "+f"(acc[0]), "+f"(acc[1]), "+f"(acc[2]), "+f"(acc[3])
        : "r"(a[0]), "r"(a[1]), "r"(a[2]), "r"(a[3]), "r"(b[0]), "r"(b[1]));
}

__global__ void __launch_bounds__(256)
gemm_tf32(const float* __restrict__ A, const float* __restrict__ B,
          float* __restrict__ C, int M, int N, int K)
{
    extern __shared__ uint32_t smem_u32[];
    const int tid  = threadIdx.x;
    const int lane = tid & 31;
    const int warp = tid >> 5;
    const int wm   = warp >> 2;     // 0..1  (rows of warp grid)
    const int wn   = warp & 3;      // 0..3  (cols of warp grid)
    const int m0   = blockIdx.y * BM;
    const int n0   = blockIdx.x * BN;

    float acc[4][4][4];
#pragma unroll
    for (int i = 0; i < 4; i++)
#pragma unroll
        for (int j = 0; j < 4; j++)
#pragma unroll
            for (int q = 0; q < 4; q++) acc[i][j][q] = 0.f;

    // per-thread global load pattern: 4 x float4 for A, 4 x float4 for B
    const int rowA = tid >> 3;            // 0..31 (step 32 per i)
    const int kq   = (tid & 7) << 2;      // 0..28
    const float* Ag = A + (size_t)(m0 + rowA) * K + kq;
    const float* Bg = B + (size_t)(n0 + rowA) * K + kq;
    const int nrow0 = n0 + rowA;

    const int KT = K / BK;
    float4 ra[4], rb[4];

    // ---- load tile 0 ----
#pragma unroll
    for (int i = 0; i < 4; i++) {
        ra[i] = *reinterpret_cast<const float4*>(Ag + (size_t)32 * i * K);
        if (nrow0 + 32 * i < N)
            rb[i] = *reinterpret_cast<const float4*>(Bg + (size_t)32 * i * K);
        else
            rb[i] = make_float4(0.f, 0.f, 0.f, 0.f);
    }
    {
        uint32_t* As0 = smem_u32;
        uint32_t* Bs0 = smem_u32 + 4096;
#pragma unroll
        for (int i = 0; i < 4; i++) {
            const int r = rowA + 32 * i;
            const float* pv = reinterpret_cast<const float*>(&ra[i]);
            const float* pw = reinterpret_cast<const float*>(&rb[i]);
#pragma unroll
            for (int j = 0; j < 4; j++) {
                As0[aidx(r, kq + j)] = f2tf(pv[j]);
                Bs0[bidx(r, kq + j)] = f2tf(pw[j]);
            }
        }
    }
    __syncthreads();

    int pb = 0;
    for (int kt = 0; kt < KT; ++kt) {
        // prefetch next tile into registers
        if (kt + 1 < KT) {
            const float* a = Ag + (size_t)(kt + 1) * BK;
            const float* b = Bg + (size_t)(kt + 1) * BK;
#pragma unroll
            for (int i = 0; i < 4; i++) {
                ra[i] = *reinterpret_cast<const float4*>(a + (size_t)32 * i * K);
                if (nrow0 + 32 * i < N)
                    rb[i] = *reinterpret_cast<const float4*>(b + (size_t)32 * i * K);
                else
                    rb[i] = make_float4(0.f, 0.f, 0.f, 0.f);
            }
        }

        // compute from buffer pb
        {
            const uint32_t* Asb = smem_u32 + pb * 8192;
            const uint32_t* Bsb = smem_u32 + pb * 8192 + 4096;
#pragma unroll
            for (int ks = 0; ks < 4; ++ks) {
                uint32_t af[4][4];
                uint32_t bf[4][2];
#pragma unroll
                for (int im = 0; im < 4; ++im) {
                    const int mt = wm * 4 + im;
                    const uint4 t = *reinterpret_cast<const uint4*>(
                        &Asb[((((ks << 3) + mt) << 5) + lane) * 4]);
                    af[im][0] = t.x; af[im][1] = t.y; af[im][2] = t.z; af[im][3] = t.w;
                }
#pragma unroll
                for (int jn = 0; jn < 4; ++jn) {
                    const int nt = wn * 4 + jn;
                    const uint2 t = *reinterpret_cast<const uint2*>(
                        &Bsb[((((ks << 4) + nt) << 5) + lane) * 2]);
                    bf[jn][0] = t.x; bf[jn][1] = t.y;
                }
#pragma unroll
                for (int im = 0; im < 4; ++im)
#pragma unroll
                    for (int jn = 0; jn < 4; ++jn)
                        mma8(acc[im][jn], af[im], bf[jn]);
            }
        }

        // stage prefetched tile into the other buffer
        if (kt + 1 < KT) {
            uint32_t* Asn = smem_u32 + (pb ^ 1) * 8192;
            uint32_t* Bsn = smem_u32 + (pb ^ 1) * 8192 + 4096;
#pragma unroll
            for (int i = 0; i < 4; i++) {
                const int r = rowA + 32 * i;
                const float* pv = reinterpret_cast<const float*>(&ra[i]);
                const float* pw = reinterpret_cast<const float*>(&rb[i]);
#pragma unroll
                for (int j = 0; j < 4; j++) {
                    Asn[aidx(r, kq + j)] = f2tf(pv[j]);
                    Bsn[bidx(r, kq + j)] = f2tf(pw[j]);
                }
            }
        }
        __syncthreads();
        pb ^= 1;
    }

    // ---- epilogue: fragment layout c0..c3 -> (g,2t),(g,2t+1),(g+8,2t),(g+8,2t+1)
    const int g = lane >> 2, t = lane & 3;
#pragma unroll
    for (int im = 0; im < 4; ++im) {
        const int mrow = m0 + wm * 64 + im * 16 + g;
#pragma unroll
        for (int jn = 0; jn < 4; ++jn) {
            const int nb = n0 + wn * 32 + jn * 8;
            if (nb < N) {   // N is always a multiple of 8 here
                float2 v0 = make_float2(acc[im][jn][0], acc[im][jn][1]);
                float2 v1 = make_float2(acc[im][jn][2], acc[im][jn][3]);
                *reinterpret_cast<float2*>(&C[(size_t)mrow * N + nb + 2 * t])       = v0;
                *reinterpret_cast<float2*>(&C[(size_t)(mrow + 8) * N + nb + 2 * t]) = v1;
            }
        }
    }
}

// ---------------------------------------------------------------------------
// Elementwise kernels
// ---------------------------------------------------------------------------
__device__ __forceinline__ float siluf(float v)     { return v / (1.f + expf(-v)); }
__device__ __forceinline__ float softplusf(float v) { return fmaxf(v, 0.f) + log1pf(expf(-fabsf(v))); }

// xc[b,l,c] = silu(conv_b[c] + sum_k conv_w[c,k] * xb[b, l+k-3, c]); xb = xz[..., :2048]
__global__ void __launch_bounds__(256)
conv_silu_kernel(const float* __restrict__ xz, const float* __restrict__ cw,
                 const float* __restrict__ cb, float* __restrict__ xc)
{
    const int idx = blockIdx.x * blockDim.x + threadIdx.x;   // NROWS*512
    const int c4 = (idx & 511) << 2;
    const int r  = idx >> 9;
    if (r >= NROWS) return;
    const int l = r & (LSEQ - 1);

    const float4 bias = *reinterpret_cast<const float4*>(&cb[c4]);
    float a0 = bias.x, a1 = bias.y, a2 = bias.z, a3 = bias.w;

#pragma unroll
    for (int k = 0; k < 4; k++) {
        const int ls = l + k - 3;
        if (ls >= 0) {
            const float4 v = *reinterpret_cast<const float4*>(
                &xz[(size_t)(r + k - 3) * NXZ + c4]);
            a0 = fmaf(__ldg(&cw[(c4 + 0) * 4 + k]), v.x, a0);
            a1 = fmaf(__ldg(&cw[(c4 + 1) * 4 + k]), v.y, a1);
            a2 = fmaf(__ldg(&cw[(c4 + 2) * 4 + k]), v.z, a2);
            a3 = fmaf(__ldg(&cw[(c4 + 3) * 4 + k]), v.w, a3);
        }
    }
    float4 o;
    o.x = siluf(a0); o.y = siluf(a1); o.z = siluf(a2); o.w = siluf(a3);
    *reinterpret_cast<float4*>(&xc[(size_t)r * DINNER + c4]) = o;
}

// y = (softplus(dproj)*bc + D) * xc * silu(z), bc = sum_s Bm[s]*Cm[s]
__global__ void __launch_bounds__(128)
combine_kernel(const float* __restrict__ xz, const float* __restrict__ xc,
               const float* __restrict__ proj, const float* __restrict__ D,
               float* __restrict__ y)
{
    const int r   = blockIdx.x;
    const int tid = threadIdx.x;
    __shared__ float sbc;

    const float* prow = proj + (size_t)r * NPROJ;
    if (tid < 32) {
        float v = 0.f;
        if (tid < D_STATE) v = prow[tid] * prow[D_STATE + tid];
#pragma unroll
        for (int o = 8; o > 0; o >>= 1) v += __shfl_xor_sync(0xffffffffu, v, o);
        if (tid == 0) sbc = v;
    }
    __syncthreads();
    const float bc = sbc;

    const float* xcrow = xc + (size_t)r * DINNER;
    const float* zrow  = xz + (size_t)r * NXZ + DINNER;
    float*       yrow  = y  + (size_t)r * DINNER;

#pragma unroll
    for (int i = 0; i < 4; i++) {
        const int c = (i * 128 + tid) * 4;
        const float4 dp = *reinterpret_cast<const float4*>(&prow[2 * D_STATE + c]);
        const float4 xv = *reinterpret_cast<const float4*>(&xcrow[c]);
        const float4 zv = *reinterpret_cast<const float4*>(&zrow[c]);
        const float4 Dv = *reinterpret_cast<const float4*>(&D[c]);
        float4 o;
        o.x = (softplusf(dp.x) * bc + Dv.x) * xv.x * siluf(zv.x);
        o.y = (softplusf(dp.y) * bc + Dv.y) * xv.y * siluf(zv.y);
        o.z = (softplusf(dp.z) * bc + Dv.z) * xv.z * siluf(zv.z);
        o.w = (softplusf(dp.w) * bc + Dv.w) * xv.w * siluf(zv.w);
        *reinterpret_cast<float4*>(&yrow[c]) = o;
    }
}

// ---------------------------------------------------------------------------
// Launch
// ---------------------------------------------------------------------------
extern "C" void kernel_launch(void* const* d_in, const int* in_sizes, int n_in,
                              void* d_out, int out_size)
{
    const float* x      = (const float*)d_in[0];
    const float* W_in   = (const float*)d_in[1];
    const float* conv_w = (const float*)d_in[2];
    const float* conv_b = (const float*)d_in[3];
    const float* W_xp   = (const float*)d_in[4];
    const float* D      = (const float*)d_in[5];
    const float* W_out  = (const float*)d_in[6];
    float* out = (float*)d_out;

    void *p_xz, *p_xc, *p_proj, *p_y;
    cudaGetSymbolAddress(&p_xz, g_xz);
    cudaGetSymbolAddress(&p_xc, g_xc);
    cudaGetSymbolAddress(&p_proj, g_proj);
    cudaGetSymbolAddress(&p_y, g_y);

    cudaFuncSetAttribute(gemm_tf32, cudaFuncAttributeMaxDynamicSharedMemorySize, 65536);

    // GEMM1: xz = x @ W_in^T     (8192 x 4096 x 1024)
    gemm_tf32<<<dim3(NXZ / BN, NROWS / BM), 256, 65536>>>(
        x, W_in, (float*)p_xz, NROWS, NXZ, DMODEL);

    // conv + SiLU
    conv_silu_kernel<<<(NROWS * 512) / 256, 256>>>(
        (const float*)p_xz, conv_w, conv_b, (float*)p_xc);

    // GEMM2: proj = xc @ W_xproj^T  (8192 x 2080 x 2048), N guarded
    gemm_tf32<<<dim3((NPROJ + BN - 1) / BN, NROWS / BM), 256, 65536>>>(
        (const float*)p_xc, W_xp, (float*)p_proj, NROWS, NPROJ, DINNER);

    // combine: y
    combine_kernel<<<NROWS, 128>>>(
        (const float*)p_xz, (const float*)p_xc, (const float*)p_proj, D, (float*)p_y);

    // GEMM3: out = y @ W_out^T   (8192 x 1024 x 2048)
    gemm_tf32<<<dim3(DMODEL / BN, NROWS / BM), 256, 65536>>>(
        (const float*)p_y, W_out, out, NROWS, DMODEL, DINNER);
}

// round 5
// speedup vs baseline: 1.0000x; 1.0000x over previous
#include <cuda_runtime.h>
#include <cstdint>

// ---------------------------------------------------------------------------
// SelectiveSSM: xz = x@W_in^T ; conv+SiLU ; proj = xc@W_xproj^T ;
// combine (bc = sum(Bm*Cm), y = (softplus(dproj)*bc + D)*xc*silu(z)) ;
// out = y@W_out^T
// All GEMMs: C[M,N] = A[M,K] * B[N,K]^T, K-contiguous both operands.
// TF32 tensor-core GEMM (mma.sync.m16n8k8), fp32 accumulate.
// ---------------------------------------------------------------------------

#define D_STATE 16
#define BSZ     2
#define LSEQ    4096
#define DMODEL  1024
#define DINNER  2048
#define NROWS   (BSZ * LSEQ)            // 8192
#define NXZ     (2 * DINNER)            // 4096
#define NPROJ   (2 * D_STATE + DINNER)  // 2080

// Scratch (device globals: allocation-free)
__device__ float g_xz[NROWS * (size_t)NXZ];      // 134 MB
__device__ float g_xc[NROWS * (size_t)DINNER];   // 67 MB
__device__ float g_proj[NROWS * (size_t)NPROJ];  // 68 MB
__device__ float g_y[NROWS * (size_t)DINNER];    // 67 MB

// ---------------------------------------------------------------------------
// TF32 GEMM
// ---------------------------------------------------------------------------
#define BM 128
#define BN 128
#define BK 32

__device__ __forceinline__ uint32_t f2tf(float x) {
    uint32_t u;
    asm("cvt.rna.tf32.f32 %0, %1;" : "=r"(u) : "f"(x));
    return u;
}

// smem layout (per buffer, units of u32):
//   As[kstep(4)][mtile(8)][lane(32)][4 regs]   = 4096 u32 (16 KB)
//   Bs[kstep(4)][ntile(16)][lane(32)][2 regs]  = 4096 u32 (16 KB)
// Fragment-native: inner loop does one LDS.128 per A frag, LDS.64 per B frag.
__device__ __forceinline__ int aidx(int row, int k) {
    int kstep = k >> 3, kin = k & 7;
    int mtile = row >> 4, r = row & 15;
    int ln  = ((r & 7) << 2) | (kin & 3);
    int reg = ((kin >> 2) << 1) | (r >> 3);
    return ((((kstep << 3) + mtile) << 5) + ln) * 4 + reg;
}
__device__ __forceinline__ int bidx(int row, int k) {
    int kstep = k >> 3, kin = k & 7;
    int ntile = row >> 3, nin = row & 7;
    int ln  = (nin << 2) | (kin & 3);
    int reg = kin >> 2;
    return ((((kstep << 4) + ntile) << 5) + ln) * 2 + reg;
}

__device__ __forceinline__ void mma8(float acc[4], const uint32_t a[4], const uint32_t b[2]) {
    asm volatile(
        "mma.sync.aligned.m16n8k8.row.col.f32.tf32.tf32.f32 "
        "{%0,%1,%2,%3}, {%4,%5,%6,%7}, {%8,%9}, {%0,%1,%2,%3};"
        : "+f"(acc[0]), "+f"(acc[1]), "+f"(acc[2]), "+f"(acc[3])
        : "r"(a[0]), "r"(a[1]), "r"(a[2]), "r"(a[3]), "r"(b[0]), "r"(b[1]));
}

__global__ void __launch_bounds__(256)
gemm_tf32(const float* __restrict__ A, const float* __restrict__ B,
          float* __restrict__ C, int M, int N, int K)
{
    extern __shared__ uint32_t smem_u32[];
    const int tid  = threadIdx.x;
    const int lane = tid & 31;
    const int warp = tid >> 5;
    const int wm   = warp >> 2;     // 0..1  (rows of warp grid)
    const int wn   = warp & 3;      // 0..3  (cols of warp grid)
    const int m0   = blockIdx.y * BM;
    const int n0   = blockIdx.x * BN;

    float acc[4][4][4];
#pragma unroll
    for (int i = 0; i < 4; i++)
#pragma unroll
        for (int j = 0; j < 4; j++)
#pragma unroll
            for (int q = 0; q < 4; q++) acc[i][j][q] = 0.f;

    // per-thread global load pattern: 4 x float4 for A, 4 x float4 for B
    const int rowA = tid >> 3;            // 0..31 (step 32 per i)
    const int kq   = (tid & 7) << 2;      // 0..28
    const float* Ag = A + (size_t)(m0 + rowA) * K + kq;
    const float* Bg = B + (size_t)(n0 + rowA) * K + kq;
    const int nrow0 = n0 + rowA;

    const int KT = K / BK;
    float4 ra[4], rb[4];

    // ---- load tile 0 ----
#pragma unroll
    for (int i = 0; i < 4; i++) {
        ra[i] = *reinterpret_cast<const float4*>(Ag + (size_t)32 * i * K);
        if (nrow0 + 32 * i < N)
            rb[i] = *reinterpret_cast<const float4*>(Bg + (size_t)32 * i * K);
        else
            rb[i] = make_float4(0.f, 0.f, 0.f, 0.f);
    }
    {
        uint32_t* As0 = smem_u32;
        uint32_t* Bs0 = smem_u32 + 4096;
#pragma unroll
        for (int i = 0; i < 4; i++) {
            const int r = rowA + 32 * i;
            const float* pv = reinterpret_cast<const float*>(&ra[i]);
            const float* pw = reinterpret_cast<const float*>(&rb[i]);
#pragma unroll
            for (int j = 0; j < 4; j++) {
                As0[aidx(r, kq + j)] = f2tf(pv[j]);
                Bs0[bidx(r, kq + j)] = f2tf(pw[j]);
            }
        }
    }
    __syncthreads();

    int pb = 0;
    for (int kt = 0; kt < KT; ++kt) {
        // prefetch next tile into registers
        if (kt + 1 < KT) {
            const float* a = Ag + (size_t)(kt + 1) * BK;
            const float* b = Bg + (size_t)(kt + 1) * BK;
#pragma unroll
            for (int i = 0; i < 4; i++) {
                ra[i] = *reinterpret_cast<const float4*>(a + (size_t)32 * i * K);
                if (nrow0 + 32 * i < N)
                    rb[i] = *reinterpret_cast<const float4*>(b + (size_t)32 * i * K);
                else
                    rb[i] = make_float4(0.f, 0.f, 0.f, 0.f);
            }
        }

        // compute from buffer pb
        {
            const uint32_t* Asb = smem_u32 + pb * 8192;
            const uint32_t* Bsb = smem_u32 + pb * 8192 + 4096;
#pragma unroll
            for (int ks = 0; ks < 4; ++ks) {
                uint32_t af[4][4];
                uint32_t bf[4][2];
#pragma unroll
                for (int im = 0; im < 4; ++im) {
                    const int mt = wm * 4 + im;
                    const uint4 t = *reinterpret_cast<const uint4*>(
                        &Asb[((((ks << 3) + mt) << 5) + lane) * 4]);
                    af[im][0] = t.x; af[im][1] = t.y; af[im][2] = t.z; af[im][3] = t.w;
                }
#pragma unroll
                for (int jn = 0; jn < 4; ++jn) {
                    const int nt = wn * 4 + jn;
                    const uint2 t = *reinterpret_cast<const uint2*>(
                        &Bsb[((((ks << 4) + nt) << 5) + lane) * 2]);
                    bf[jn][0] = t.x; bf[jn][1] = t.y;
                }
#pragma unroll
                for (int im = 0; im < 4; ++im)
#pragma unroll
                    for (int jn = 0; jn < 4; ++jn)
                        mma8(acc[im][jn], af[im], bf[jn]);
            }
        }

        // stage prefetched tile into the other buffer
        if (kt + 1 < KT) {
            uint32_t* Asn = smem_u32 + (pb ^ 1) * 8192;
            uint32_t* Bsn = smem_u32 + (pb ^ 1) * 8192 + 4096;
#pragma unroll
            for (int i = 0; i < 4; i++) {
                const int r = rowA + 32 * i;
                const float* pv = reinterpret_cast<const float*>(&ra[i]);
                const float* pw = reinterpret_cast<const float*>(&rb[i]);
#pragma unroll
                for (int j = 0; j < 4; j++) {
                    Asn[aidx(r, kq + j)] = f2tf(pv[j]);
                    Bsn[bidx(r, kq + j)] = f2tf(pw[j]);
                }
            }
        }
        __syncthreads();
        pb ^= 1;
    }

    // ---- epilogue: fragment layout c0..c3 -> (g,2t),(g,2t+1),(g+8,2t),(g+8,2t+1)
    const int g = lane >> 2, t = lane & 3;
#pragma unroll
    for (int im = 0; im < 4; ++im) {
        const int mrow = m0 + wm * 64 + im * 16 + g;
#pragma unroll
        for (int jn = 0; jn < 4; ++jn) {
            const int nb = n0 + wn * 32 + jn * 8;
            if (nb < N) {   // N is always a multiple of 8 here
                float2 v0 = make_float2(acc[im][jn][0], acc[im][jn][1]);
                float2 v1 = make_float2(acc[im][jn][2], acc[im][jn][3]);
                *reinterpret_cast<float2*>(&C[(size_t)mrow * N + nb + 2 * t])       = v0;
                *reinterpret_cast<float2*>(&C[(size_t)(mrow + 8) * N + nb + 2 * t]) = v1;
            }
        }
    }
}

// ---------------------------------------------------------------------------
// Elementwise kernels
// ---------------------------------------------------------------------------
__device__ __forceinline__ float siluf(float v)     { return v / (1.f + expf(-v)); }
__device__ __forceinline__ float softplusf(float v) { return fmaxf(v, 0.f) + log1pf(expf(-fabsf(v))); }

// xc[b,l,c] = silu(conv_b[c] + sum_k conv_w[c,k] * xb[b, l+k-3, c]); xb = xz[..., :2048]
__global__ void __launch_bounds__(256)
conv_silu_kernel(const float* __restrict__ xz, const float* __restrict__ cw,
                 const float* __restrict__ cb, float* __restrict__ xc)
{
    const int idx = blockIdx.x * blockDim.x + threadIdx.x;   // NROWS*512
    const int c4 = (idx & 511) << 2;
    const int r  = idx >> 9;
    if (r >= NROWS) return;
    const int l = r & (LSEQ - 1);

    const float4 bias = *reinterpret_cast<const float4*>(&cb[c4]);
    float a0 = bias.x, a1 = bias.y, a2 = bias.z, a3 = bias.w;

#pragma unroll
    for (int k = 0; k < 4; k++) {
        const int ls = l + k - 3;
        if (ls >= 0) {
            const float4 v = *reinterpret_cast<const float4*>(
                &xz[(size_t)(r + k - 3) * NXZ + c4]);
            a0 = fmaf(__ldg(&cw[(c4 + 0) * 4 + k]), v.x, a0);
            a1 = fmaf(__ldg(&cw[(c4 + 1) * 4 + k]), v.y, a1);
            a2 = fmaf(__ldg(&cw[(c4 + 2) * 4 + k]), v.z, a2);
            a3 = fmaf(__ldg(&cw[(c4 + 3) * 4 + k]), v.w, a3);
        }
    }
    float4 o;
    o.x = siluf(a0); o.y = siluf(a1); o.z = siluf(a2); o.w = siluf(a3);
    *reinterpret_cast<float4*>(&xc[(size_t)r * DINNER + c4]) = o;
}

// y = (softplus(dproj)*bc + D) * xc * silu(z), bc = sum_s Bm[s]*Cm[s]
__global__ void __launch_bounds__(128)
combine_kernel(const float* __restrict__ xz, const float* __restrict__ xc,
               const float* __restrict__ proj, const float* __restrict__ D,
               float* __restrict__ y)
{
    const int r   = blockIdx.x;
    const int tid = threadIdx.x;
    __shared__ float sbc;

    const float* prow = proj + (size_t)r * NPROJ;
    if (tid < 32) {
        float v = 0.f;
        if (tid < D_STATE) v = prow[tid] * prow[D_STATE + tid];
#pragma unroll
        for (int o = 8; o > 0; o >>= 1) v += __shfl_xor_sync(0xffffffffu, v, o);
        if (tid == 0) sbc = v;
    }
    __syncthreads();
    const float bc = sbc;

    const float* xcrow = xc + (size_t)r * DINNER;
    const float* zrow  = xz + (size_t)r * NXZ + DINNER;
    float*       yrow  = y  + (size_t)r * DINNER;

#pragma unroll
    for (int i = 0; i < 4; i++) {
        const int c = (i * 128 + tid) * 4;
        const float4 dp = *reinterpret_cast<const float4*>(&prow[2 * D_STATE + c]);
        const float4 xv = *reinterpret_cast<const float4*>(&xcrow[c]);
        const float4 zv = *reinterpret_cast<const float4*>(&zrow[c]);
        const float4 Dv = *reinterpret_cast<const float4*>(&D[c]);
        float4 o;
        o.x = (softplusf(dp.x) * bc + Dv.x) * xv.x * siluf(zv.x);
        o.y = (softplusf(dp.y) * bc + Dv.y) * xv.y * siluf(zv.y);
        o.z = (softplusf(dp.z) * bc + Dv.z) * xv.z * siluf(zv.z);
        o.w = (softplusf(dp.w) * bc + Dv.w) * xv.w * siluf(zv.w);
        *reinterpret_cast<float4*>(&yrow[c]) = o;
    }
}

// ---------------------------------------------------------------------------
// Launch
// ---------------------------------------------------------------------------
extern "C" void kernel_launch(void* const* d_in, const int* in_sizes, int n_in,
                              void* d_out, int out_size)
{
    const float* x      = (const float*)d_in[0];
    const float* W_in   = (const float*)d_in[1];
    const float* conv_w = (const float*)d_in[2];
    const float* conv_b = (const float*)d_in[3];
    const float* W_xp   = (const float*)d_in[4];
    const float* D      = (const float*)d_in[5];
    const float* W_out  = (const float*)d_in[6];
    float* out = (float*)d_out;

    void *p_xz, *p_xc, *p_proj, *p_y;
    cudaGetSymbolAddress(&p_xz, g_xz);
    cudaGetSymbolAddress(&p_xc, g_xc);
    cudaGetSymbolAddress(&p_proj, g_proj);
    cudaGetSymbolAddress(&p_y, g_y);

    cudaFuncSetAttribute(gemm_tf32, cudaFuncAttributeMaxDynamicSharedMemorySize, 65536);

    // GEMM1: xz = x @ W_in^T     (8192 x 4096 x 1024)
    gemm_tf32<<<dim3(NXZ / BN, NROWS / BM), 256, 65536>>>(
        x, W_in, (float*)p_xz, NROWS, NXZ, DMODEL);

    // conv + SiLU
    conv_silu_kernel<<<(NROWS * 512) / 256, 256>>>(
        (const float*)p_xz, conv_w, conv_b, (float*)p_xc);

    // GEMM2: proj = xc @ W_xproj^T  (8192 x 2080 x 2048), N guarded
    gemm_tf32<<<dim3((NPROJ + BN - 1) / BN, NROWS / BM), 256, 65536>>>(
        (const float*)p_xc, W_xp, (float*)p_proj, NROWS, NPROJ, DINNER);

    // combine: y
    combine_kernel<<<NROWS, 128>>>(
        (const float*)p_xz, (const float*)p_xc, (const float*)p_proj, D, (float*)p_y);

    // GEMM3: out = y @ W_out^T   (8192 x 1024 x 2048)
    gemm_tf32<<<dim3(DMODEL / BN, NROWS / BM), 256, 65536>>>(
        (const float*)p_y, W_out, out, NROWS, DMODEL, DINNER);
}

// round 7
// speedup vs baseline: 2.0025x; 2.0024x over previous
#include <cuda_runtime.h>
#include <cstdint>

// ---------------------------------------------------------------------------
// SelectiveSSM on GB300 (harness assembles for base sm_103 => no tcgen05).
// Strategy: mma.sync.m16n8k8 tf32 GEMMs with ZERO-cost staging:
//   - all GEMM operands pre-rounded to tf32 (RNA) AND pre-permuted into
//     fragment-major global layout (the exact smem layout the compute loop
//     reads with LDS.128/LDS.64),
//   - GEMM staging is an identity copy done with cp.async.cg 16B,
//   - conv/combine epilogues write their outputs directly in fragment layout.
// Compute loop + epilogue are byte-identical to the R5 kernel that passed
// with rel_err 5.1e-4.
// ---------------------------------------------------------------------------

#define D_STATE 16
#define BSZ     2
#define LSEQ    4096
#define DMODEL  1024
#define DINNER  2048
#define NROWS   (BSZ * LSEQ)            // 8192
#define NXZ     (2 * DINNER)            // 4096
#define NPROJ   (2 * D_STATE + DINNER)  // 2080
#define NPROJ_PAD 2176                  // 17 * 128

// Scratch (device globals: allocation-free)
__device__ float g_xz[NROWS * (size_t)NXZ];        // GEMM1 out (normal layout)
__device__ float g_proj[NROWS * (size_t)NPROJ];    // GEMM2 out (normal layout)
// fragment-major operands
__device__ float g_xf[NROWS * (size_t)DMODEL];         // x        (A, GEMM1)
__device__ float g_winf[NXZ * (size_t)DMODEL];         // W_in     (B, GEMM1)
__device__ float g_xcf[NROWS * (size_t)DINNER];        // xc       (A, GEMM2)
__device__ float g_wxpf[NPROJ_PAD * (size_t)DINNER];   // W_xproj  (B, GEMM2, padded)
__device__ float g_yf[NROWS * (size_t)DINNER];         // y        (A, GEMM3)
__device__ float g_woutf[DMODEL * (size_t)DINNER];     // W_out    (B, GEMM3)

// ---------------------------------------------------------------------------
// Fragment layout (identical to the validated R5 smem layout).
// Per 128x32 tile: 4096 u32.
//   A: [kstep(4)][mtile(8)][lane(32)][4 regs]
//   B: [kstep(4)][ntile(16)][lane(32)][2 regs]
// ---------------------------------------------------------------------------
__device__ __forceinline__ int aidx(int row, int k) {
    int kstep = k >> 3, kin = k & 7;
    int mtile = row >> 4, r = row & 15;
    int ln  = ((r & 7) << 2) | (kin & 3);
    int reg = ((kin >> 2) << 1) | (r >> 3);
    return ((((kstep << 3) + mtile) << 5) + ln) * 4 + reg;
}
__device__ __forceinline__ int bidx(int row, int k) {
    int kstep = k >> 3, kin = k & 7;
    int ntile = row >> 3, nin = row & 7;
    int ln  = (nin << 2) | (kin & 3);
    int reg = kin >> 2;
    return ((((kstep << 4) + ntile) << 5) + ln) * 2 + reg;
}

// RNA round-to-tf32 on raw bits (== cvt.rna.tf32.f32; container stays f32).
__device__ __forceinline__ uint32_t rtf32(float f) {
    return (__float_as_uint(f) + 0x1000u) & 0xFFFFE000u;
}

__device__ __forceinline__ void mma8(float acc[4], const uint32_t a[4], const uint32_t b[2]) {
    asm volatile(
        "mma.sync.aligned.m16n8k8.row.col.f32.tf32.tf32.f32 "
        "{%0,%1,%2,%3}, {%4,%5,%6,%7}, {%8,%9}, {%0,%1,%2,%3};"
        : "+f"(acc[0]), "+f"(acc[1]), "+f"(acc[2]), "+f"(acc[3])
        : "r"(a[0]), "r"(a[1]), "r"(a[2]), "r"(a[3]), "r"(b[0]), "r"(b[1]));
}

#define CP_ASYNC16(dst_u32, src_ptr) \
    asm volatile("cp.async.cg.shared.global [%0], [%1], 16;" \
                 :: "r"(dst_u32), "l"(src_ptr) : "memory")
#define CP_COMMIT() asm volatile("cp.async.commit_group;" ::: "memory")
#define CP_WAIT0()  asm volatile("cp.async.wait_group 0;" ::: "memory")

__device__ __forceinline__ uint32_t smem_u32a(const void* p) {
    uint32_t a;
    asm("{ .reg .u64 t; cvta.to.shared.u64 t, %1; cvt.u32.u64 %0, t; }"
        : "=r"(a) : "l"(p));
    return a;
}

// ---------------------------------------------------------------------------
// GEMM: C[M,N] = A[M,K] * B[N,K]^T, operands in fragment-major global layout.
// Tile 128x128, BK=32, 256 threads, 2x4 warp grid (64x32 per warp).
// smem: 2 buffers x (A 16KB + B 16KB) = 64 KB dynamic.
// ---------------------------------------------------------------------------
__global__ void __launch_bounds__(256, 2)
gemm_frag(const float* __restrict__ Af, const float* __restrict__ Bf,
          float* __restrict__ C, int M, int N, int KT /* = K/32 */)
{
    extern __shared__ uint32_t smem[];   // 16384 u32 (two 8192-u32 buffers)
    const int tid  = threadIdx.x;
    const int lane = tid & 31;
    const int warp = tid >> 5;
    const int wm   = warp >> 2;
    const int wn   = warp & 3;
    const int m0   = blockIdx.y * 128;
    const int n0   = blockIdx.x * 128;

    const uint32_t sb = smem_u32a(smem);
    const float* At = Af + ((size_t)blockIdx.y * KT) * 4096;
    const float* Bt = Bf + ((size_t)blockIdx.x * KT) * 4096;

    float acc[4][4][4];
#pragma unroll
    for (int i = 0; i < 4; i++)
#pragma unroll
        for (int j = 0; j < 4; j++)
#pragma unroll
            for (int q = 0; q < 4; q++) acc[i][j][q] = 0.f;

    // ---- prologue: stage tile 0 into buffer 0
#pragma unroll
    for (int i = 0; i < 4; i++) {
        const int slot = tid + 256 * i;                 // float4 slot
        CP_ASYNC16(sb + (uint32_t)slot * 16,         At + (size_t)slot * 4);
        CP_ASYNC16(sb + 16384u + (uint32_t)slot * 16, Bt + (size_t)slot * 4);
    }
    CP_COMMIT();

    for (int kt = 0; kt < KT; ++kt) {
        CP_WAIT0();
        __syncthreads();

        // stage next tile into the other buffer (overlaps compute below)
        if (kt + 1 < KT) {
            const uint32_t boff = ((kt + 1) & 1) ? 32768u : 0u;
            const float* An = At + (size_t)(kt + 1) * 4096;
            const float* Bn = Bt + (size_t)(kt + 1) * 4096;
#pragma unroll
            for (int i = 0; i < 4; i++) {
                const int slot = tid + 256 * i;
                CP_ASYNC16(sb + boff + (uint32_t)slot * 16,          An + (size_t)slot * 4);
                CP_ASYNC16(sb + boff + 16384u + (uint32_t)slot * 16, Bn + (size_t)slot * 4);
            }
            CP_COMMIT();
        }

        // ---- compute from buffer kt&1 (identical to the validated R5 loop)
        const uint32_t* Asb = smem + (kt & 1) * 8192;
        const uint32_t* Bsb = Asb + 4096;
#pragma unroll
        for (int ks = 0; ks < 4; ++ks) {
            uint32_t af[4][4];
            uint32_t bf[4][2];
#pragma unroll
            for (int im = 0; im < 4; ++im) {
                const int mt = wm * 4 + im;
                const uint4 t = *reinterpret_cast<const uint4*>(
                    &Asb[((((ks << 3) + mt) << 5) + lane) * 4]);
                af[im][0] = t.x; af[im][1] = t.y; af[im][2] = t.z; af[im][3] = t.w;
            }
#pragma unroll
            for (int jn = 0; jn < 4; ++jn) {
                const int nt = wn * 4 + jn;
                const uint2 t = *reinterpret_cast<const uint2*>(
                    &Bsb[((((ks << 4) + nt) << 5) + lane) * 2]);
                bf[jn][0] = t.x; bf[jn][1] = t.y;
            }
#pragma unroll
            for (int im = 0; im < 4; ++im)
#pragma unroll
                for (int jn = 0; jn < 4; ++jn)
                    mma8(acc[im][jn], af[im], bf[jn]);
        }
    }

    // ---- epilogue (identical to R5)
    const int g = lane >> 2, t = lane & 3;
#pragma unroll
    for (int im = 0; im < 4; ++im) {
        const int mrow = m0 + wm * 64 + im * 16 + g;
#pragma unroll
        for (int jn = 0; jn < 4; ++jn) {
            const int nb = n0 + wn * 32 + jn * 8;
            if (nb < N) {
                float2 v0 = make_float2(acc[im][jn][0], acc[im][jn][1]);
                float2 v1 = make_float2(acc[im][jn][2], acc[im][jn][3]);
                *reinterpret_cast<float2*>(&C[(size_t)mrow * N + nb + 2 * t])       = v0;
                *reinterpret_cast<float2*>(&C[(size_t)(mrow + 8) * N + nb + 2 * t]) = v1;
            }
        }
    }
}

// ---------------------------------------------------------------------------
// Prep: round to tf32 + permute into fragment-major layout
// ---------------------------------------------------------------------------
__global__ void __launch_bounds__(256)
prep_frag_a(const float* __restrict__ src, float* __restrict__ dst, int M, int K)
{
    const int idx = blockIdx.x * blockDim.x + threadIdx.x;  // M*K/4 threads
    const int kp = K >> 2;
    const int r  = idx / kp;
    const int kq = (idx - r * kp) << 2;
    if (r >= M) return;
    const float4 v = *reinterpret_cast<const float4*>(&src[(size_t)r * K + kq]);
    uint32_t* d = reinterpret_cast<uint32_t*>(dst) +
                  ((size_t)((r >> 7) * (K >> 5) + (kq >> 5))) * 4096;
    const int rr = r & 127, kk = kq & 31;
    d[aidx(rr, kk + 0)] = rtf32(v.x);
    d[aidx(rr, kk + 1)] = rtf32(v.y);
    d[aidx(rr, kk + 2)] = rtf32(v.z);
    d[aidx(rr, kk + 3)] = rtf32(v.w);
}

__global__ void __launch_bounds__(256)
prep_frag_b(const float* __restrict__ src, float* __restrict__ dst,
            int Nr, int K, int Npad)
{
    const int idx = blockIdx.x * blockDim.x + threadIdx.x;  // Npad*K/4 threads
    const int kp = K >> 2;
    const int r  = idx / kp;
    const int kq = (idx - r * kp) << 2;
    if (r >= Npad) return;
    float4 v = make_float4(0.f, 0.f, 0.f, 0.f);
    if (r < Nr) v = *reinterpret_cast<const float4*>(&src[(size_t)r * K + kq]);
    uint32_t* d = reinterpret_cast<uint32_t*>(dst) +
                  ((size_t)((r >> 7) * (K >> 5) + (kq >> 5))) * 4096;
    const int rr = r & 127, kk = kq & 31;
    d[bidx(rr, kk + 0)] = rtf32(v.x);
    d[bidx(rr, kk + 1)] = rtf32(v.y);
    d[bidx(rr, kk + 2)] = rtf32(v.z);
    d[bidx(rr, kk + 3)] = rtf32(v.w);
}

// ---------------------------------------------------------------------------
// Elementwise
// ---------------------------------------------------------------------------
__device__ __forceinline__ float siluf(float v)     { return v / (1.f + expf(-v)); }
__device__ __forceinline__ float softplusf(float v) { return fmaxf(v, 0.f) + log1pf(expf(-fabsf(v))); }

// fragment-A offset for activation matrices with K=DINNER (GEMM2/3 A operand)
__device__ __forceinline__ size_t fragA_off(int r, int c) {
    return ((size_t)((r >> 7) * (DINNER >> 5) + (c >> 5))) * 4096 + aidx(r & 127, c & 31);
}

// xc = tf32(silu(conv(xb))), written in fragment-A layout (feeds GEMM2)
__global__ void __launch_bounds__(256)
conv_silu_kernel(const float* __restrict__ xz, const float* __restrict__ cw,
                 const float* __restrict__ cb, float* __restrict__ xcf)
{
    const int idx = blockIdx.x * blockDim.x + threadIdx.x;
    const int c4 = (idx & 511) << 2;
    const int r  = idx >> 9;
    if (r >= NROWS) return;
    const int l = r & (LSEQ - 1);

    const float4 bias = *reinterpret_cast<const float4*>(&cb[c4]);
    float a0 = bias.x, a1 = bias.y, a2 = bias.z, a3 = bias.w;

#pragma unroll
    for (int k = 0; k < 4; k++) {
        const int ls = l + k - 3;
        if (ls >= 0) {
            const float4 v = *reinterpret_cast<const float4*>(
                &xz[(size_t)(r + k - 3) * NXZ + c4]);
            a0 = fmaf(__ldg(&cw[(c4 + 0) * 4 + k]), v.x, a0);
            a1 = fmaf(__ldg(&cw[(c4 + 1) * 4 + k]), v.y, a1);
            a2 = fmaf(__ldg(&cw[(c4 + 2) * 4 + k]), v.z, a2);
            a3 = fmaf(__ldg(&cw[(c4 + 3) * 4 + k]), v.w, a3);
        }
    }
    uint32_t* d = reinterpret_cast<uint32_t*>(xcf);
    const size_t base = ((size_t)((r >> 7) * (DINNER >> 5) + (c4 >> 5))) * 4096;
    const int rr = r & 127, kk = c4 & 31;
    d[base + aidx(rr, kk + 0)] = rtf32(siluf(a0));
    d[base + aidx(rr, kk + 1)] = rtf32(siluf(a1));
    d[base + aidx(rr, kk + 2)] = rtf32(siluf(a2));
    d[base + aidx(rr, kk + 3)] = rtf32(siluf(a3));
}

// y = tf32((softplus(dproj)*bc + D) * xc * silu(z)), fragment-A layout (feeds GEMM3)
__global__ void __launch_bounds__(128)
combine_kernel(const float* __restrict__ xz, const float* __restrict__ xcf,
               const float* __restrict__ proj, const float* __restrict__ D,
               float* __restrict__ yf)
{
    const int r   = blockIdx.x;
    const int tid = threadIdx.x;
    __shared__ float sbc;

    const float* prow = proj + (size_t)r * NPROJ;
    if (tid < 32) {
        float v = 0.f;
        if (tid < D_STATE) v = prow[tid] * prow[D_STATE + tid];
#pragma unroll
        for (int o = 8; o > 0; o >>= 1) v += __shfl_xor_sync(0xffffffffu, v, o);
        if (tid == 0) sbc = v;
    }
    __syncthreads();
    const float bc = sbc;

    const uint32_t* xcu = reinterpret_cast<const uint32_t*>(xcf);
    uint32_t*       yu  = reinterpret_cast<uint32_t*>(yf);
    const float*    zrow = xz + (size_t)r * NXZ + DINNER;
    const int rr = r & 127;
    const size_t rowbase = ((size_t)(r >> 7) * (DINNER >> 5)) * 4096;

#pragma unroll
    for (int i = 0; i < 4; i++) {
        const int c = (i * 128 + tid) * 4;
        const float4 dp = *reinterpret_cast<const float4*>(&prow[2 * D_STATE + c]);
        const float4 zv = *reinterpret_cast<const float4*>(&zrow[c]);
        const float4 Dv = *reinterpret_cast<const float4*>(&D[c]);
        const size_t base = rowbase + (size_t)(c >> 5) * 4096;
        const int kk = c & 31;
        const float x0 = __uint_as_float(xcu[base + aidx(rr, kk + 0)]);
        const float x1 = __uint_as_float(xcu[base + aidx(rr, kk + 1)]);
        const float x2 = __uint_as_float(xcu[base + aidx(rr, kk + 2)]);
        const float x3 = __uint_as_float(xcu[base + aidx(rr, kk + 3)]);
        yu[base + aidx(rr, kk + 0)] = rtf32((softplusf(dp.x) * bc + Dv.x) * x0 * siluf(zv.x));
        yu[base + aidx(rr, kk + 1)] = rtf32((softplusf(dp.y) * bc + Dv.y) * x1 * siluf(zv.y));
        yu[base + aidx(rr, kk + 2)] = rtf32((softplusf(dp.z) * bc + Dv.z) * x2 * siluf(zv.z));
        yu[base + aidx(rr, kk + 3)] = rtf32((softplusf(dp.w) * bc + Dv.w) * x3 * siluf(zv.w));
    }
}

// ---------------------------------------------------------------------------
// Launch
// ---------------------------------------------------------------------------
extern "C" void kernel_launch(void* const* d_in, const int* in_sizes, int n_in,
                              void* d_out, int out_size)
{
    const float* x      = (const float*)d_in[0];
    const float* W_in   = (const float*)d_in[1];
    const float* conv_w = (const float*)d_in[2];
    const float* conv_b = (const float*)d_in[3];
    const float* W_xp   = (const float*)d_in[4];
    const float* D      = (const float*)d_in[5];
    const float* W_out  = (const float*)d_in[6];
    float* out = (float*)d_out;

    void *p_xz, *p_proj, *p_xf, *p_winf, *p_xcf, *p_wxpf, *p_yf, *p_woutf;
    cudaGetSymbolAddress(&p_xz,    g_xz);
    cudaGetSymbolAddress(&p_proj,  g_proj);
    cudaGetSymbolAddress(&p_xf,    g_xf);
    cudaGetSymbolAddress(&p_winf,  g_winf);
    cudaGetSymbolAddress(&p_xcf,   g_xcf);
    cudaGetSymbolAddress(&p_wxpf,  g_wxpf);
    cudaGetSymbolAddress(&p_yf,    g_yf);
    cudaGetSymbolAddress(&p_woutf, g_woutf);

    cudaFuncSetAttribute(gemm_frag, cudaFuncAttributeMaxDynamicSharedMemorySize, 65536);

    // Prep: tf32-round + fragment-permute the GEMM operands
    prep_frag_a<<<(NROWS * (DMODEL / 4)) / 256, 256>>>(x, (float*)p_xf, NROWS, DMODEL);
    prep_frag_b<<<(NXZ * (DMODEL / 4)) / 256, 256>>>(W_in, (float*)p_winf, NXZ, DMODEL, NXZ);
    prep_frag_b<<<(NPROJ_PAD * (DINNER / 4)) / 256, 256>>>(W_xp, (float*)p_wxpf, NPROJ, DINNER, NPROJ_PAD);
    prep_frag_b<<<(DMODEL * (DINNER / 4)) / 256, 256>>>(W_out, (float*)p_woutf, DMODEL, DINNER, DMODEL);

    // GEMM1: xz = x @ W_in^T   (8192 x 4096 x 1024)
    gemm_frag<<<dim3(NXZ / 128, NROWS / 128), 256, 65536>>>(
        (const float*)p_xf, (const float*)p_winf, (float*)p_xz,
        NROWS, NXZ, DMODEL / 32);

    // conv + SiLU -> xc (fragment layout)
    conv_silu_kernel<<<(NROWS * 512) / 256, 256>>>(
        (const float*)p_xz, conv_w, conv_b, (float*)p_xcf);

    // GEMM2: proj = xc @ W_xproj^T  (8192 x 2080 x 2048), N padded to 2176
    gemm_frag<<<dim3(NPROJ_PAD / 128, NROWS / 128), 256, 65536>>>(
        (const float*)p_xcf, (const float*)p_wxpf, (float*)p_proj,
        NROWS, NPROJ, DINNER / 32);

    // combine -> y (fragment layout)
    combine_kernel<<<NROWS, 128>>>(
        (const float*)p_xz, (const float*)p_xcf, (const float*)p_proj, D, (float*)p_yf);

    // GEMM3: out = y @ W_out^T   (8192 x 1024 x 2048)
    gemm_frag<<<dim3(DMODEL / 128, NROWS / 128), 256, 65536>>>(
        (const float*)p_yf, (const float*)p_woutf, out,
        NROWS, DMODEL, DINNER / 32);
}